// round 10
// baseline (speedup 1.0000x reference)
#include <cuda_runtime.h>

#define NB   32768
#define NCO  64
#define NDG  2048
#define NCA  256
#define KACT 81
#define MR   16
#define NTHR 256
#define STR  16   // float stride of [256 col][16 row] tiles

// ---------------- device-global scratch ----------------
__device__ float4 g_Wpp4[16 * NDG];      // [k4][c]
__device__ float  g_WmossyT[NDG * NCA];  // [d][c]
__device__ float4 g_Wrec4[64 * NCA];     // [j4][c], pre-scaled by 1.4 (=2*GAIN)
__device__ float4 g_Wcssc4[64 * NCA];    // (Wcs @ Wsc)
__device__ float4 g_Wogsc4[64 * NCA];    // 2*(Wog @ Wsc)
__device__ float4 g_Wogta4[16 * NCA];    // 2*(Wog @ Wta)
__device__ float4 g_Wcdta4[16 * NCA];    // (Wcd @ Wta)
__device__ float  g_btap[NCA];           // Wcd @ b_ta
__device__ float  g_bcssc[NCA];          // Wcs @ b_sc
__device__ float  g_b2ogta[NCA];         // 2*(Wog @ b_ta) + 2*b_og
__device__ float  g_b2ogsc[NCA];         // 2*(Wog @ b_sc) + 2*b_og
__device__ float  g_part[256 * NCO];

// order-preserving float->uint key
__device__ __forceinline__ unsigned f2u(float f){
    unsigned u = __float_as_uint(f);
    return u ^ ((u & 0x80000000u) ? 0xFFFFFFFFu : 0x80000000u);
}

// tanh where z = 2x is already applied: tanh(x) = 1 - 2/(exp(2x)+1)
__device__ __forceinline__ float fast_tanh_z(float z){
    float e = __expf(z);
    return 1.f - __fdividef(2.f, e + 1.f);
}

// 1 col x 16 rows: 4 broadcast LDS.128 per 16 FFMA
__device__ __forceinline__ void fma1x16(float acc[16], const float* __restrict__ sT, float w){
    const float4* e = (const float4*)sT;
    float4 v0 = e[0], v1 = e[1], v2 = e[2], v3 = e[3];
    acc[0] = fmaf(v0.x, w, acc[0]);  acc[1] = fmaf(v0.y, w, acc[1]);
    acc[2] = fmaf(v0.z, w, acc[2]);  acc[3] = fmaf(v0.w, w, acc[3]);
    acc[4] = fmaf(v1.x, w, acc[4]);  acc[5] = fmaf(v1.y, w, acc[5]);
    acc[6] = fmaf(v1.z, w, acc[6]);  acc[7] = fmaf(v1.w, w, acc[7]);
    acc[8] = fmaf(v2.x, w, acc[8]);  acc[9] = fmaf(v2.y, w, acc[9]);
    acc[10]= fmaf(v2.z, w, acc[10]); acc[11]= fmaf(v2.w, w, acc[11]);
    acc[12]= fmaf(v3.x, w, acc[12]); acc[13]= fmaf(v3.y, w, acc[13]);
    acc[14]= fmaf(v3.z, w, acc[14]); acc[15]= fmaf(v3.w, w, acc[15]);
}

// 1 col x 8 rows
__device__ __forceinline__ void fma1x8(float acc[8], const float* __restrict__ sT, float w){
    const float4* e = (const float4*)sT;
    float4 v0 = e[0], v1 = e[1];
    acc[0] = fmaf(v0.x, w, acc[0]);  acc[1] = fmaf(v0.y, w, acc[1]);
    acc[2] = fmaf(v0.z, w, acc[2]);  acc[3] = fmaf(v0.w, w, acc[3]);
    acc[4] = fmaf(v1.x, w, acc[4]);  acc[5] = fmaf(v1.y, w, acc[5]);
    acc[6] = fmaf(v1.z, w, acc[6]);  acc[7] = fmaf(v1.w, w, acc[7]);
}

// GEMV over 256 inputs: thread owns col c, all 16 rows (each weight read ONCE per block)
__device__ __forceinline__ void gemv256_c(float acc[16], const float* __restrict__ src,
                                          const float4* __restrict__ w4, int c){
    #pragma unroll 4
    for (int j4 = 0; j4 < 64; ++j4){
        float4 wv = w4[j4 * NCA + c];
        fma1x16(acc, src + (4*j4+0)*STR, wv.x);
        fma1x16(acc, src + (4*j4+1)*STR, wv.y);
        fma1x16(acc, src + (4*j4+2)*STR, wv.z);
        fma1x16(acc, src + (4*j4+3)*STR, wv.w);
    }
}

// GEMV over 64 inputs (reads s_ecT [64][16])
__device__ __forceinline__ void gemv64_c(float acc[16], const float* __restrict__ src,
                                         const float4* __restrict__ w4, int c){
    #pragma unroll 4
    for (int k4 = 0; k4 < 16; ++k4){
        float4 wv = w4[k4 * NCA + c];
        fma1x16(acc, src + (4*k4+0)*STR, wv.x);
        fma1x16(acc, src + (4*k4+1)*STR, wv.y);
        fma1x16(acc, src + (4*k4+2)*STR, wv.z);
        fma1x16(acc, src + (4*k4+3)*STR, wv.w);
    }
}

__device__ __forceinline__ void store16(float* __restrict__ dst, const float acc[16], int c){
    float4* d = (float4*)(dst + c*STR);
    d[0] = make_float4(acc[0], acc[1], acc[2], acc[3]);
    d[1] = make_float4(acc[4], acc[5], acc[6], acc[7]);
    d[2] = make_float4(acc[8], acc[9], acc[10], acc[11]);
    d[3] = make_float4(acc[12], acc[13], acc[14], acc[15]);
}

// ---------------- prep kernel: coalesced relayouts + column partial sums ----------------
__global__ void prep_kernel(const float* __restrict__ coords,
                            const float* __restrict__ W_pp, const float* __restrict__ W_mo,
                            const float* __restrict__ W_rec)
{
    __shared__ float sh[32 * 65];
    const int b = blockIdx.x, tid = threadIdx.x;
    const int tx = tid & 31, ty = tid >> 5;   // 32 x 8

    if (b < 256){
        __shared__ float s[4][64];
        int c = tid & 63, g = tid >> 6;
        int r0 = b * 128 + g * 32;
        float acc = 0.f;
        #pragma unroll 8
        for (int i = 0; i < 32; ++i) acc += coords[(r0 + i) * 64 + c];
        s[g][c] = acc;
        __syncthreads();
        if (g == 0) g_part[b * 64 + c] = s[0][c] + s[1][c] + s[2][c] + s[3][c];
    } else if (b < 768){
        // W_mossy transpose: W_mo[c][d] (256x2048) -> g_WmossyT[d][c]
        int b2 = b - 256;
        int ci = b2 & 7, di = b2 >> 3;
        #pragma unroll
        for (int i = 0; i < 4; ++i){
            int cc = ty + 8 * i;
            sh[cc * 33 + tx] = W_mo[(ci * 32 + cc) * 2048 + di * 32 + tx];
        }
        __syncthreads();
        #pragma unroll
        for (int i = 0; i < 4; ++i){
            int dd = ty + 8 * i;
            g_WmossyT[(di * 32 + dd) * 256 + ci * 32 + tx] = sh[tx * 33 + dd];
        }
    } else if (b < 832){
        // W_pp relayout: W_pp[c][k] (2048x64) -> g_Wpp4[k4*2048 + c]
        int c0 = (b - 768) * 32;
        #pragma unroll
        for (int i = 0; i < 8; ++i){
            int idx = i * 256 + tid;
            int row = idx >> 6, col = idx & 63;
            sh[row * 65 + col] = W_pp[(c0 + row) * 64 + col];
        }
        __syncthreads();
        #pragma unroll
        for (int oi = 0; oi < 2; ++oi){
            int idx = oi * 256 + tid;
            int k4 = idx >> 5, c = idx & 31;
            float4 v = make_float4(sh[c * 65 + 4*k4], sh[c * 65 + 4*k4 + 1],
                                   sh[c * 65 + 4*k4 + 2], sh[c * 65 + 4*k4 + 3]);
            g_Wpp4[k4 * NDG + c0 + c] = v;
        }
    } else {
        // W_rec relayout: W_rec[c][j] (256x256) -> g_Wrec4[j4*256 + c], scaled 1.4
        int b4 = b - 832;
        int ci = b4 & 7, ji = b4 >> 3;
        #pragma unroll
        for (int i = 0; i < 4; ++i){
            int cc = ty + 8 * i;
            sh[cc * 33 + tx] = W_rec[(ci * 32 + cc) * 256 + ji * 32 + tx];
        }
        __syncthreads();
        {
            int j4l = ty, c = tx;
            float4 v = make_float4(1.4f * sh[c * 33 + 4*j4l],     1.4f * sh[c * 33 + 4*j4l + 1],
                                   1.4f * sh[c * 33 + 4*j4l + 2], 1.4f * sh[c * 33 + 4*j4l + 3]);
            g_Wrec4[(ji * 8 + j4l) * NCA + ci * 32 + c] = v;
        }
    }
}

// ---------------- tiled GEMM prep + bias dots ----------------
__global__ void prep_gemm(const float* __restrict__ W_cs, const float* __restrict__ W_cd,
                          const float* __restrict__ W_og,
                          const float* __restrict__ W_sc, const float* __restrict__ W_ta,
                          const float* __restrict__ b_ta, const float* __restrict__ b_sc,
                          const float* __restrict__ b_og)
{
    int b = blockIdx.x;
    int tx = threadIdx.x & 31;
    int ty = threadIdx.x >> 5;

    if (b >= 160){
        // bias dot: dst[c] = scale * sum_k A[c][k] * vec[k] (+ 2*b_og for og paths)
        int t = b - 160;
        const float* A   = (t==0) ? W_cd : (t==1) ? W_cs : W_og;
        const float* vec = (t==0) ? b_ta : (t==1) ? b_sc : (t==2) ? b_ta : b_sc;
        float* dst = (t==0) ? g_btap : (t==1) ? g_bcssc : (t==2) ? g_b2ogta : g_b2ogsc;
        float scale = (t < 2) ? 1.f : 2.f;
        for (int c = ty; c < 256; c += 8){
            float acc = 0.f;
            #pragma unroll
            for (int kt = 0; kt < 8; ++kt)
                acc = fmaf(A[c * 256 + kt * 32 + tx], vec[kt * 32 + tx], acc);
            #pragma unroll
            for (int o = 16; o; o >>= 1) acc += __shfl_xor_sync(~0u, acc, o);
            if (tx == 0) dst[c] = scale * acc + ((t >= 2) ? 2.f * b_og[c] : 0.f);
        }
        return;
    }

    __shared__ float As[32][33];
    __shared__ float Bs[32][33];

    const float *A, *B; float* dst; float scale; int ldb, jtiles;
    if (b < 64)      { A = W_cs; B = W_sc; dst = (float*)g_Wcssc4; scale = 1.f; ldb = 256; jtiles = 8; }
    else if (b < 128){ A = W_og; B = W_sc; dst = (float*)g_Wogsc4; scale = 2.f; ldb = 256; jtiles = 8; b -= 64; }
    else if (b < 144){ A = W_og; B = W_ta; dst = (float*)g_Wogta4; scale = 2.f; ldb = 64;  jtiles = 2; b -= 128; }
    else             { A = W_cd; B = W_ta; dst = (float*)g_Wcdta4; scale = 1.f; ldb = 64;  jtiles = 2; b -= 144; }

    int ci = b / jtiles, ji = b % jtiles;
    float acc[4] = {0.f, 0.f, 0.f, 0.f};
    for (int kt = 0; kt < 8; ++kt){
        #pragma unroll
        for (int ii = 0; ii < 4; ++ii){
            int rr = ty + 8 * ii;
            As[rr][tx] = A[(ci * 32 + rr) * 256 + kt * 32 + tx];
            Bs[rr][tx] = B[(kt * 32 + rr) * ldb + ji * 32 + tx];
        }
        __syncthreads();
        #pragma unroll
        for (int kk = 0; kk < 32; ++kk){
            float bv = Bs[kk][tx];
            #pragma unroll
            for (int ii = 0; ii < 4; ++ii)
                acc[ii] = fmaf(As[ty + 8 * ii][kk], bv, acc[ii]);
        }
        __syncthreads();
    }

    #pragma unroll
    for (int ii = 0; ii < 4; ++ii)
        As[ty + 8 * ii][tx] = scale * acc[ii];
    __syncthreads();
    {
        int j4l = ty, cl = tx;
        int j0 = ji * 32 + j4l * 4;
        float4 v = make_float4(As[cl][j4l*4], As[cl][j4l*4+1], As[cl][j4l*4+2], As[cl][j4l*4+3]);
        ((float4*)dst)[(j0 >> 2) * NCA + ci * 32 + cl] = v;
    }
}

// ---------------- fused pipeline: 16 rows per block, 2 blocks/SM ----------------
extern "C" __global__ void __launch_bounds__(NTHR, 2)
fused_kernel(const float* __restrict__ coords,
             const float* __restrict__ ec_g,  const float* __restrict__ ec_b,
             const float* __restrict__ b_pp,
             const float* __restrict__ dg_g,  const float* __restrict__ dg_b,
             float* __restrict__ out)
{
    extern __shared__ float sm[];
    float*    B1       = sm;
    float*    B2       = sm + 4096;
    float*    B3       = sm + 8192;
    float*    pool     = sm;                      // union with B1..B3 + 4096 extra
    float*    s_ecT    = sm + 16384;              // [64][16] = 1024
    float2*   s_act    = (float2*)(sm + 17408);   // 16 x 84 float2 = 2688 floats
    unsigned* s_hist   = (unsigned*)(sm + 20096); // 8 x 256 = 2048
    float*    s_tmp    = sm + 22144;              // 256
    float*    s_bufadd = sm + 22400;              // 64
    float*    s_nov    = sm + 22464;              // 16
    float*    s_red    = sm + 22480;              // 8 warps x 48 = 384

    const int tid  = threadIdx.x;
    const int w    = tid >> 5;
    const int lane = tid & 31;
    const unsigned lmask = (1u << lane) - 1u;
    const int row0 = blockIdx.x * MR;

    // ---- Stage 0: reduce column partials -> s_bufadd ----
    {
        int c = tid & 63, q = tid >> 6;
        float a = 0.f;
        #pragma unroll 8
        for (int i = 0; i < 64; ++i) a += g_part[(q * 64 + i) * 64 + c];
        s_tmp[q * 64 + c] = a;
        __syncthreads();
        if (tid < 64)
            s_bufadd[tid] = (0.05f / (float)NB) *
                (s_tmp[tid] + s_tmp[64 + tid] + s_tmp[128 + tid] + s_tmp[192 + tid]);
        __syncthreads();
    }

    // ---- Stage 1: EC layernorm (2 rows/warp) -> s_ecT[64][16] ----
    for (int rr = 0; rr < 2; ++rr){
        int r  = w * 2 + rr;
        int gr = row0 + r;
        float v1 = coords[gr*64 + lane]      + s_bufadd[lane];
        float v2 = coords[gr*64 + lane + 32] + s_bufadd[lane + 32];
        float s = v1 + v2, s2 = v1*v1 + v2*v2;
        #pragma unroll
        for (int o = 16; o; o >>= 1){ s += __shfl_xor_sync(~0u, s, o); s2 += __shfl_xor_sync(~0u, s2, o); }
        float mu = s * (1.f/64.f);
        float rs = rsqrtf(s2 * (1.f/64.f) - mu*mu + 1e-5f);
        s_ecT[lane*16 + r]      = (v1 - mu) * rs * ec_g[lane]      + ec_b[lane];
        s_ecT[(lane+32)*16 + r] = (v2 - mu) * rs * ec_g[lane + 32] + ec_b[lane + 32];
    }
    __syncthreads();

    // ---- Stages 2-4: two passes of 8 rows: proj GEMM + LN + 3-pass radix top-81 ----
    for (int p = 0; p < 2; ++p){
        // proj: thread owns col c = nt*256+tid, 8 rows; each Wpp weight read once
        for (int nt = 0; nt < 8; ++nt){
            int c = nt * 256 + tid;
            float bp = b_pp[c];
            float a8[8] = {bp, bp, bp, bp, bp, bp, bp, bp};
            #pragma unroll 4
            for (int k4 = 0; k4 < 16; ++k4){
                float4 wv = g_Wpp4[k4 * NDG + c];
                fma1x8(a8, s_ecT + (4*k4+0)*16 + p*8, wv.x);
                fma1x8(a8, s_ecT + (4*k4+1)*16 + p*8, wv.y);
                fma1x8(a8, s_ecT + (4*k4+2)*16 + p*8, wv.z);
                fma1x8(a8, s_ecT + (4*k4+3)*16 + p*8, wv.w);
            }
            #pragma unroll
            for (int i = 0; i < 8; ++i)
                pool[i*NDG + c] = fmaxf(a8[i], 0.f);
        }
        __syncthreads();

        // 1 row per warp: LN + 3-pass radix (24-bit threshold) + compaction
        {
            unsigned* hist = s_hist + w * 256;
            int rg  = p * 8 + w;
            float* row = pool + w * NDG;
            float s = 0.f, s2 = 0.f;
            for (int i = lane; i < NDG; i += 32){ float v = row[i]; s += v; s2 += v*v; }
            #pragma unroll
            for (int o = 16; o; o >>= 1){ s += __shfl_xor_sync(~0u, s, o); s2 += __shfl_xor_sync(~0u, s2, o); }
            float mu = s * (1.f/2048.f);
            float rs = rsqrtf(s2 * (1.f/2048.f) - mu*mu + 1e-5f);
            for (int i = lane; i < NDG; i += 32)
                row[i] = (row[i] - mu) * rs * dg_g[i] + dg_b[i];
            __syncwarp();

            unsigned prefix = 0; int need = KACT;
            for (int pp = 3; pp >= 1; --pp){
                for (int b = lane; b < 256; b += 32) hist[b] = 0;
                __syncwarp();
                unsigned himask = (pp == 3) ? 0u : (0xFFFFFFFFu << ((pp + 1) * 8));
                for (int i = lane; i < NDG; i += 32){
                    unsigned uu = f2u(row[i]);
                    if ((uu & himask) == prefix) atomicAdd(&hist[(uu >> (pp*8)) & 255], 1u);
                }
                __syncwarp();
                int b0 = 255 - lane * 8;
                unsigned cs[8]; unsigned cnt = 0;
                #pragma unroll
                for (int t = 0; t < 8; ++t){ cs[t] = hist[b0 - t]; cnt += cs[t]; }
                unsigned inc = cnt;
                #pragma unroll
                for (int o = 1; o < 32; o <<= 1){ unsigned v = __shfl_up_sync(~0u, inc, o); if (lane >= o) inc += v; }
                unsigned excl = inc - cnt;
                bool hit = (excl < (unsigned)need) && ((unsigned)need <= inc);
                unsigned bal = __ballot_sync(~0u, hit);
                int srcl = __ffs(bal) - 1;
                int selbin = 0, newneed = 0, found = 0;
                if (hit){
                    unsigned cum = excl;
                    #pragma unroll
                    for (int t = 0; t < 8; ++t){
                        unsigned nc = cum + cs[t];
                        if (!found && nc >= (unsigned)need){ selbin = b0 - t; newneed = need - (int)cum; found = 1; }
                        cum = nc;
                    }
                }
                selbin = __shfl_sync(~0u, selbin, srcl);
                need   = __shfl_sync(~0u, newneed, srcl);
                prefix |= ((unsigned)selbin) << (pp * 8);
            }

            int base = 0, ties = 0;
            for (int g = 0; g < 64; ++g){
                int c = g * 32 + lane;
                float v = row[c];
                unsigned uu = f2u(v) & 0xFFFFFF00u;
                bool eq = (uu == prefix);
                bool gt = (uu >  prefix);
                unsigned beq = __ballot_sync(~0u, eq);
                int tr = ties + __popc(beq & lmask);
                bool act = gt || (eq && tr < need);
                unsigned ba = __ballot_sync(~0u, act);
                if (act){
                    int pos = base + __popc(ba & lmask);
                    s_act[rg*84 + pos] = make_float2(v, __int_as_float(c << 8));
                }
                base += __popc(ba);
                ties += __popc(beq);
            }
        }
        __syncthreads();
    }

    // ---- Stage 5: cue = sparse(dg) @ WmossyT -> B1[256][STR] ----
    {
        float acc[16];
        #pragma unroll
        for (int r = 0; r < 16; ++r) acc[r] = 0.f;
        #pragma unroll 2
        for (int a = 0; a < KACT; ++a){
            #pragma unroll
            for (int r = 0; r < 16; ++r){
                float2 pv = s_act[r*84 + a];
                acc[r] = fmaf(pv.x, g_WmossyT[__float_as_int(pv.y) + tid], acc[r]);
            }
        }
        store16(B1, acc, tid);
    }
    __syncthreads();

    // ---- Stage 6: 5-step settle; z = state@(1.4*Wrec)^T + 0.6*cue; tanh via exp(z) ----
    float cuev[16];
    {
        const float4* cp = (const float4*)(B1 + tid*STR);
        float4 x0 = cp[0], x1 = cp[1], x2 = cp[2], x3 = cp[3];
        cuev[0]=0.6f*x0.x; cuev[1]=0.6f*x0.y; cuev[2]=0.6f*x0.z; cuev[3]=0.6f*x0.w;
        cuev[4]=0.6f*x1.x; cuev[5]=0.6f*x1.y; cuev[6]=0.6f*x1.z; cuev[7]=0.6f*x1.w;
        cuev[8]=0.6f*x2.x; cuev[9]=0.6f*x2.y; cuev[10]=0.6f*x2.z; cuev[11]=0.6f*x2.w;
        cuev[12]=0.6f*x3.x; cuev[13]=0.6f*x3.y; cuev[14]=0.6f*x3.z; cuev[15]=0.6f*x3.w;
    }
    const float* cur = B1;
    float* nxt = B2;
    for (int it = 0; it < 5; ++it){
        float acc[16];
        #pragma unroll
        for (int r = 0; r < 16; ++r) acc[r] = 0.f;
        gemv256_c(acc, cur, g_Wrec4, tid);
        float res[16];
        #pragma unroll
        for (int r = 0; r < 16; ++r) res[r] = fast_tanh_z(acc[r] + cuev[r]);
        store16(nxt, res, tid);
        __syncthreads();
        if (it == 0){ cur = B2; nxt = B3; }
        else { float* t = (float*)cur; cur = nxt; nxt = t; }
    }
    // final state in B2

    // ---- Stage 8: s_proj = state@(WcsWsc)^T + b ; d_proj = ec@(WcdWta)^T + b ; fused novelty ----
    {
        float acc_s[16];
        float sb = g_bcssc[tid];
        #pragma unroll
        for (int r = 0; r < 16; ++r) acc_s[r] = sb;
        gemv256_c(acc_s, B2, g_Wcssc4, tid);

        float acc_d[16];
        float db = g_btap[tid];
        #pragma unroll
        for (int r = 0; r < 16; ++r) acc_d[r] = db;
        gemv64_c(acc_d, s_ecT, g_Wcdta4, tid);

        // per-row partials over this thread's single column; fixed-order reduction
        #pragma unroll
        for (int r = 0; r < 16; ++r){
            float sd = acc_s[r]*acc_d[r];
            float sn = acc_s[r]*acc_s[r];
            float dn = acc_d[r]*acc_d[r];
            #pragma unroll
            for (int o = 16; o; o >>= 1){
                sd += __shfl_xor_sync(~0u, sd, o);
                sn += __shfl_xor_sync(~0u, sn, o);
                dn += __shfl_xor_sync(~0u, dn, o);
            }
            if (lane == 0){
                s_red[w*48 + r*3 + 0] = sd;
                s_red[w*48 + r*3 + 1] = sn;
                s_red[w*48 + r*3 + 2] = dn;
            }
        }
    }
    __syncthreads();
    if (tid < 16){
        int r = tid;
        float sd = 0.f, sn = 0.f, dn = 0.f;
        #pragma unroll
        for (int q = 0; q < 8; ++q){
            sd += s_red[q*48 + r*3 + 0];
            sn += s_red[q*48 + r*3 + 1];
            dn += s_red[q*48 + r*3 + 2];
        }
        float s_n = fmaxf(sqrtf(sn), 1e-8f);
        float d_n = fmaxf(sqrtf(dn), 1e-8f);
        float cosv = sd / (s_n * d_n);
        float nov = fminf(fmaxf(1.f - cosv, 0.f), 1.f);
        s_nov[r] = nov;
        out[(long long)NB * NCA + row0 + r] = nov;
    }
    __syncthreads();

    // ---- Stage 10: out = tanh( g*A + (1-g)*B ), 2x and b_og folded into A,B ----
    {
        float accA[16];
        float ab = g_b2ogta[tid];
        #pragma unroll
        for (int r = 0; r < 16; ++r) accA[r] = ab;
        gemv64_c(accA, s_ecT, g_Wogta4, tid);

        float accB[16];
        float bb = g_b2ogsc[tid];
        #pragma unroll
        for (int r = 0; r < 16; ++r) accB[r] = bb;
        gemv256_c(accB, B2, g_Wogsc4, tid);

        #pragma unroll
        for (int r = 0; r < 16; ++r){
            float g = s_nov[r];
            float z = fmaf(g, accA[r], (1.f - g) * accB[r]);
            out[(long long)(row0 + r) * NCA + tid] = fast_tanh_z(z);
        }
    }
}

// ---------------- launch ----------------
extern "C" void kernel_launch(void* const* d_in, const int* in_sizes, int n_in,
                              void* d_out, int out_size)
{
    const float* coords = (const float*)d_in[0];
    const float* ec_g   = (const float*)d_in[1];
    const float* ec_b   = (const float*)d_in[2];
    const float* W_pp   = (const float*)d_in[3];
    const float* b_pp   = (const float*)d_in[4];
    const float* dg_g   = (const float*)d_in[5];
    const float* dg_b   = (const float*)d_in[6];
    const float* W_mo   = (const float*)d_in[7];
    const float* W_rec  = (const float*)d_in[8];
    const float* W_sc   = (const float*)d_in[9];
    const float* b_sc   = (const float*)d_in[10];
    const float* W_ta   = (const float*)d_in[11];
    const float* b_ta   = (const float*)d_in[12];
    const float* W_cs   = (const float*)d_in[13];
    const float* W_cd   = (const float*)d_in[14];
    const float* W_og   = (const float*)d_in[15];
    const float* b_og   = (const float*)d_in[16];
    float* out = (float*)d_out;

    // smem floats: union 16384 + ecT 1024 + act 2688 + hist 2048 + tmp 256 + bufadd 64 + nov 16 + red 384
    const size_t smem = (size_t)(16384 + 1024 + 2688 + 2048 + 256 + 64 + 16 + 384) * 4;  // 91,456 B
    static int configured = 0;
    if (!configured){
        cudaFuncSetAttribute(fused_kernel, cudaFuncAttributeMaxDynamicSharedMemorySize, (int)smem);
        configured = 1;
    }

    prep_kernel<<<896, 256>>>(coords, W_pp, W_mo, W_rec);
    prep_gemm<<<164, 256>>>(W_cs, W_cd, W_og, W_sc, W_ta, b_ta, b_sc, b_og);
    fused_kernel<<<NB / MR, NTHR, smem>>>(coords, ec_g, ec_b, b_pp, dg_g, dg_b, out);
}

// round 11
// speedup vs baseline: 1.1305x; 1.1305x over previous
#include <cuda_runtime.h>

#define NB   32768
#define NCO  64
#define NDG  2048
#define NCA  256
#define KACT 81
#define MR   16
#define NTHR 256
#define STR  16   // float stride of [256 col][16 row] tiles

// ---------------- device-global scratch ----------------
__device__ float4 g_Wpp4[16 * NDG];      // [k4][c]
__device__ float  g_WmossyT[NDG * NCA];  // [d][c]
__device__ float4 g_Wrec4[64 * NCA];     // [j4][c], pre-scaled by 1.4 (=2*GAIN)
__device__ float4 g_Wcssc4[64 * NCA];    // (Wcs @ Wsc)
__device__ float4 g_Wogsc4[64 * NCA];    // 2*(Wog @ Wsc)
__device__ float4 g_Wogta4[16 * NCA];    // 2*(Wog @ Wta)
__device__ float4 g_Wcdta4[16 * NCA];    // (Wcd @ Wta)
__device__ float  g_btap[NCA];           // Wcd @ b_ta
__device__ float  g_bcssc[NCA];          // Wcs @ b_sc
__device__ float  g_b2ogta[NCA];         // 2*(Wog @ b_ta) + 2*b_og
__device__ float  g_b2ogsc[NCA];         // 2*(Wog @ b_sc) + 2*b_og
__device__ float  g_part[256 * NCO];

// order-preserving float->uint key
__device__ __forceinline__ unsigned f2u(float f){
    unsigned u = __float_as_uint(f);
    return u ^ ((u & 0x80000000u) ? 0xFFFFFFFFu : 0x80000000u);
}

// tanh where z = 2x is already applied: tanh(x) = 1 - 2/(exp(2x)+1)
__device__ __forceinline__ float fast_tanh_z(float z){
    float e = __expf(z);
    return 1.f - __fdividef(2.f, e + 1.f);
}

// 2 cols x 8 rows: 2 broadcast LDS.128 per 16 FFMA
__device__ __forceinline__ void fma2x8(float acc[16], const float* __restrict__ sT,
                                       float wA, float wB){
    const float4* e = (const float4*)sT;
    float4 v0 = e[0], v1 = e[1];
    acc[0] = fmaf(v0.x, wA, acc[0]);  acc[1] = fmaf(v0.y, wA, acc[1]);
    acc[2] = fmaf(v0.z, wA, acc[2]);  acc[3] = fmaf(v0.w, wA, acc[3]);
    acc[4] = fmaf(v1.x, wA, acc[4]);  acc[5] = fmaf(v1.y, wA, acc[5]);
    acc[6] = fmaf(v1.z, wA, acc[6]);  acc[7] = fmaf(v1.w, wA, acc[7]);
    acc[8] = fmaf(v0.x, wB, acc[8]);  acc[9] = fmaf(v0.y, wB, acc[9]);
    acc[10]= fmaf(v0.z, wB, acc[10]); acc[11]= fmaf(v0.w, wB, acc[11]);
    acc[12]= fmaf(v1.x, wB, acc[12]); acc[13]= fmaf(v1.y, wB, acc[13]);
    acc[14]= fmaf(v1.z, wB, acc[14]); acc[15]= fmaf(v1.w, wB, acc[15]);
}

// paired variant: two accumulator sets share one value load
__device__ __forceinline__ void fma2x8_pair(float accP[16], float accQ[16],
                                            const float* __restrict__ sT,
                                            float pA, float pB, float qA, float qB){
    const float4* e = (const float4*)sT;
    float4 v0 = e[0], v1 = e[1];
    accP[0] = fmaf(v0.x, pA, accP[0]);  accP[1] = fmaf(v0.y, pA, accP[1]);
    accP[2] = fmaf(v0.z, pA, accP[2]);  accP[3] = fmaf(v0.w, pA, accP[3]);
    accP[4] = fmaf(v1.x, pA, accP[4]);  accP[5] = fmaf(v1.y, pA, accP[5]);
    accP[6] = fmaf(v1.z, pA, accP[6]);  accP[7] = fmaf(v1.w, pA, accP[7]);
    accP[8] = fmaf(v0.x, pB, accP[8]);  accP[9] = fmaf(v0.y, pB, accP[9]);
    accP[10]= fmaf(v0.z, pB, accP[10]); accP[11]= fmaf(v0.w, pB, accP[11]);
    accP[12]= fmaf(v1.x, pB, accP[12]); accP[13]= fmaf(v1.y, pB, accP[13]);
    accP[14]= fmaf(v1.z, pB, accP[14]); accP[15]= fmaf(v1.w, pB, accP[15]);
    accQ[0] = fmaf(v0.x, qA, accQ[0]);  accQ[1] = fmaf(v0.y, qA, accQ[1]);
    accQ[2] = fmaf(v0.z, qA, accQ[2]);  accQ[3] = fmaf(v0.w, qA, accQ[3]);
    accQ[4] = fmaf(v1.x, qA, accQ[4]);  accQ[5] = fmaf(v1.y, qA, accQ[5]);
    accQ[6] = fmaf(v1.z, qA, accQ[6]);  accQ[7] = fmaf(v1.w, qA, accQ[7]);
    accQ[8] = fmaf(v0.x, qB, accQ[8]);  accQ[9] = fmaf(v0.y, qB, accQ[9]);
    accQ[10]= fmaf(v0.z, qB, accQ[10]); accQ[11]= fmaf(v0.w, qB, accQ[11]);
    accQ[12]= fmaf(v1.x, qB, accQ[12]); accQ[13]= fmaf(v1.y, qB, accQ[13]);
    accQ[14]= fmaf(v1.z, qB, accQ[14]); accQ[15]= fmaf(v1.w, qB, accQ[15]);
}

// GEMV over 256 inputs: thread covers cols (c0, c0+128), rows rb..rb+7
__device__ __forceinline__ void gemv256(float acc[16], const float* __restrict__ src,
                                        const float4* __restrict__ w4, int c0, int rb){
    #pragma unroll 4
    for (int j4 = 0; j4 < 64; ++j4){
        float4 wa = w4[j4 * NCA + c0];
        float4 wb = w4[j4 * NCA + c0 + 128];
        fma2x8(acc, src + (4*j4+0)*STR + rb, wa.x, wb.x);
        fma2x8(acc, src + (4*j4+1)*STR + rb, wa.y, wb.y);
        fma2x8(acc, src + (4*j4+2)*STR + rb, wa.z, wb.z);
        fma2x8(acc, src + (4*j4+3)*STR + rb, wa.w, wb.w);
    }
}

// paired GEMV over 256 inputs: two weight matrices, shared value reads
__device__ __forceinline__ void gemv256_pair(float accP[16], float accQ[16],
                                             const float* __restrict__ src,
                                             const float4* __restrict__ wp,
                                             const float4* __restrict__ wq,
                                             int c0, int rb){
    #pragma unroll 2
    for (int j4 = 0; j4 < 64; ++j4){
        float4 pa = wp[j4 * NCA + c0];
        float4 pb = wp[j4 * NCA + c0 + 128];
        float4 qa = wq[j4 * NCA + c0];
        float4 qb = wq[j4 * NCA + c0 + 128];
        fma2x8_pair(accP, accQ, src + (4*j4+0)*STR + rb, pa.x, pb.x, qa.x, qb.x);
        fma2x8_pair(accP, accQ, src + (4*j4+1)*STR + rb, pa.y, pb.y, qa.y, qb.y);
        fma2x8_pair(accP, accQ, src + (4*j4+2)*STR + rb, pa.z, pb.z, qa.z, qb.z);
        fma2x8_pair(accP, accQ, src + (4*j4+3)*STR + rb, pa.w, pb.w, qa.w, qb.w);
    }
}

// paired GEMV over 64 inputs (reads s_ecT [64][16])
__device__ __forceinline__ void gemv64_pair(float accP[16], float accQ[16],
                                            const float* __restrict__ src,
                                            const float4* __restrict__ wp,
                                            const float4* __restrict__ wq,
                                            int c0, int rb){
    #pragma unroll 2
    for (int k4 = 0; k4 < 16; ++k4){
        float4 pa = wp[k4 * NCA + c0];
        float4 pb = wp[k4 * NCA + c0 + 128];
        float4 qa = wq[k4 * NCA + c0];
        float4 qb = wq[k4 * NCA + c0 + 128];
        fma2x8_pair(accP, accQ, src + (4*k4+0)*16 + rb, pa.x, pb.x, qa.x, qb.x);
        fma2x8_pair(accP, accQ, src + (4*k4+1)*16 + rb, pa.y, pb.y, qa.y, qb.y);
        fma2x8_pair(accP, accQ, src + (4*k4+2)*16 + rb, pa.z, pb.z, qa.z, qb.z);
        fma2x8_pair(accP, accQ, src + (4*k4+3)*16 + rb, pa.w, pb.w, qa.w, qb.w);
    }
}

__device__ __forceinline__ void store2x8(float* __restrict__ dst, const float acc[16],
                                         int c0, int rb){
    float4* d0 = (float4*)(dst + c0*STR + rb);
    float4* d1 = (float4*)(dst + (c0+128)*STR + rb);
    d0[0] = make_float4(acc[0], acc[1], acc[2], acc[3]);
    d0[1] = make_float4(acc[4], acc[5], acc[6], acc[7]);
    d1[0] = make_float4(acc[8], acc[9], acc[10], acc[11]);
    d1[1] = make_float4(acc[12], acc[13], acc[14], acc[15]);
}

// ---------------- prep kernel: coalesced relayouts + column partial sums ----------------
__global__ void prep_kernel(const float* __restrict__ coords,
                            const float* __restrict__ W_pp, const float* __restrict__ W_mo,
                            const float* __restrict__ W_rec)
{
    __shared__ float sh[32 * 65];
    const int b = blockIdx.x, tid = threadIdx.x;
    const int tx = tid & 31, ty = tid >> 5;   // 32 x 8

    if (b < 256){
        __shared__ float s[4][64];
        int c = tid & 63, g = tid >> 6;
        int r0 = b * 128 + g * 32;
        float acc = 0.f;
        #pragma unroll 8
        for (int i = 0; i < 32; ++i) acc += coords[(r0 + i) * 64 + c];
        s[g][c] = acc;
        __syncthreads();
        if (g == 0) g_part[b * 64 + c] = s[0][c] + s[1][c] + s[2][c] + s[3][c];
    } else if (b < 768){
        int b2 = b - 256;
        int ci = b2 & 7, di = b2 >> 3;
        #pragma unroll
        for (int i = 0; i < 4; ++i){
            int cc = ty + 8 * i;
            sh[cc * 33 + tx] = W_mo[(ci * 32 + cc) * 2048 + di * 32 + tx];
        }
        __syncthreads();
        #pragma unroll
        for (int i = 0; i < 4; ++i){
            int dd = ty + 8 * i;
            g_WmossyT[(di * 32 + dd) * 256 + ci * 32 + tx] = sh[tx * 33 + dd];
        }
    } else if (b < 832){
        int c0 = (b - 768) * 32;
        #pragma unroll
        for (int i = 0; i < 8; ++i){
            int idx = i * 256 + tid;
            int row = idx >> 6, col = idx & 63;
            sh[row * 65 + col] = W_pp[(c0 + row) * 64 + col];
        }
        __syncthreads();
        #pragma unroll
        for (int oi = 0; oi < 2; ++oi){
            int idx = oi * 256 + tid;
            int k4 = idx >> 5, c = idx & 31;
            float4 v = make_float4(sh[c * 65 + 4*k4], sh[c * 65 + 4*k4 + 1],
                                   sh[c * 65 + 4*k4 + 2], sh[c * 65 + 4*k4 + 3]);
            g_Wpp4[k4 * NDG + c0 + c] = v;
        }
    } else {
        int b4 = b - 832;
        int ci = b4 & 7, ji = b4 >> 3;
        #pragma unroll
        for (int i = 0; i < 4; ++i){
            int cc = ty + 8 * i;
            sh[cc * 33 + tx] = W_rec[(ci * 32 + cc) * 256 + ji * 32 + tx];
        }
        __syncthreads();
        {
            int j4l = ty, c = tx;
            float4 v = make_float4(1.4f * sh[c * 33 + 4*j4l],     1.4f * sh[c * 33 + 4*j4l + 1],
                                   1.4f * sh[c * 33 + 4*j4l + 2], 1.4f * sh[c * 33 + 4*j4l + 3]);
            g_Wrec4[(ji * 8 + j4l) * NCA + ci * 32 + c] = v;
        }
    }
}

// ---------------- tiled GEMM prep + bias dots ----------------
__global__ void prep_gemm(const float* __restrict__ W_cs, const float* __restrict__ W_cd,
                          const float* __restrict__ W_og,
                          const float* __restrict__ W_sc, const float* __restrict__ W_ta,
                          const float* __restrict__ b_ta, const float* __restrict__ b_sc,
                          const float* __restrict__ b_og)
{
    int b = blockIdx.x;
    int tx = threadIdx.x & 31;
    int ty = threadIdx.x >> 5;

    if (b >= 160){
        int t = b - 160;
        const float* A   = (t==0) ? W_cd : (t==1) ? W_cs : W_og;
        const float* vec = (t==0) ? b_ta : (t==1) ? b_sc : (t==2) ? b_ta : b_sc;
        float* dst = (t==0) ? g_btap : (t==1) ? g_bcssc : (t==2) ? g_b2ogta : g_b2ogsc;
        float scale = (t < 2) ? 1.f : 2.f;
        for (int c = ty; c < 256; c += 8){
            float acc = 0.f;
            #pragma unroll
            for (int kt = 0; kt < 8; ++kt)
                acc = fmaf(A[c * 256 + kt * 32 + tx], vec[kt * 32 + tx], acc);
            #pragma unroll
            for (int o = 16; o; o >>= 1) acc += __shfl_xor_sync(~0u, acc, o);
            if (tx == 0) dst[c] = scale * acc + ((t >= 2) ? 2.f * b_og[c] : 0.f);
        }
        return;
    }

    __shared__ float As[32][33];
    __shared__ float Bs[32][33];

    const float *A, *B; float* dst; float scale; int ldb, jtiles;
    if (b < 64)      { A = W_cs; B = W_sc; dst = (float*)g_Wcssc4; scale = 1.f; ldb = 256; jtiles = 8; }
    else if (b < 128){ A = W_og; B = W_sc; dst = (float*)g_Wogsc4; scale = 2.f; ldb = 256; jtiles = 8; b -= 64; }
    else if (b < 144){ A = W_og; B = W_ta; dst = (float*)g_Wogta4; scale = 2.f; ldb = 64;  jtiles = 2; b -= 128; }
    else             { A = W_cd; B = W_ta; dst = (float*)g_Wcdta4; scale = 1.f; ldb = 64;  jtiles = 2; b -= 144; }

    int ci = b / jtiles, ji = b % jtiles;
    float acc[4] = {0.f, 0.f, 0.f, 0.f};
    for (int kt = 0; kt < 8; ++kt){
        #pragma unroll
        for (int ii = 0; ii < 4; ++ii){
            int rr = ty + 8 * ii;
            As[rr][tx] = A[(ci * 32 + rr) * 256 + kt * 32 + tx];
            Bs[rr][tx] = B[(kt * 32 + rr) * ldb + ji * 32 + tx];
        }
        __syncthreads();
        #pragma unroll
        for (int kk = 0; kk < 32; ++kk){
            float bv = Bs[kk][tx];
            #pragma unroll
            for (int ii = 0; ii < 4; ++ii)
                acc[ii] = fmaf(As[ty + 8 * ii][kk], bv, acc[ii]);
        }
        __syncthreads();
    }

    #pragma unroll
    for (int ii = 0; ii < 4; ++ii)
        As[ty + 8 * ii][tx] = scale * acc[ii];
    __syncthreads();
    {
        int j4l = ty, cl = tx;
        int j0 = ji * 32 + j4l * 4;
        float4 v = make_float4(As[cl][j4l*4], As[cl][j4l*4+1], As[cl][j4l*4+2], As[cl][j4l*4+3]);
        ((float4*)dst)[(j0 >> 2) * NCA + ci * 32 + cl] = v;
    }
}

// ---------------- fused pipeline: 16 rows per block, 2 blocks/SM ----------------
extern "C" __global__ void __launch_bounds__(NTHR, 2)
fused_kernel(const float* __restrict__ coords,
             const float* __restrict__ ec_g,  const float* __restrict__ ec_b,
             const float* __restrict__ b_pp,
             const float* __restrict__ dg_g,  const float* __restrict__ dg_b,
             float* __restrict__ out)
{
    extern __shared__ float sm[];
    float*    B1       = sm;
    float*    B2       = sm + 4096;
    float*    B3       = sm + 8192;
    float*    pool     = sm;                      // union with B1..B3 + 4096 extra
    float*    s_ecT    = sm + 16384;              // [64][16] = 1024
    float2*   s_act    = (float2*)(sm + 17408);   // 16 x 84 float2 = 2688 floats
    unsigned* s_hist   = (unsigned*)(sm + 20096); // 8 x 256 = 2048
    float*    s_tmp    = sm + 22144;              // 256
    float*    s_bufadd = sm + 22400;              // 64
    float*    s_nov    = sm + 22464;              // 16
    float*    s_red    = sm + 22480;              // 8 warps x 24 = 192

    const int tid  = threadIdx.x;
    const int w    = tid >> 5;
    const int lane = tid & 31;
    const unsigned lmask = (1u << lane) - 1u;
    const int row0 = blockIdx.x * MR;
    const int c0   = tid & 127;          // col pair (c0, c0+128)
    const int rb   = (tid >> 7) * 8;     // row group (0 or 8)

    // ---- Stage 0: reduce column partials -> s_bufadd ----
    {
        int c = tid & 63, q = tid >> 6;
        float a = 0.f;
        #pragma unroll 8
        for (int i = 0; i < 64; ++i) a += g_part[(q * 64 + i) * 64 + c];
        s_tmp[q * 64 + c] = a;
        __syncthreads();
        if (tid < 64)
            s_bufadd[tid] = (0.05f / (float)NB) *
                (s_tmp[tid] + s_tmp[64 + tid] + s_tmp[128 + tid] + s_tmp[192 + tid]);
        __syncthreads();
    }

    // ---- Stage 1: EC layernorm (2 rows/warp) -> s_ecT[64][16] ----
    for (int rr = 0; rr < 2; ++rr){
        int r  = w * 2 + rr;
        int gr = row0 + r;
        float v1 = coords[gr*64 + lane]      + s_bufadd[lane];
        float v2 = coords[gr*64 + lane + 32] + s_bufadd[lane + 32];
        float s = v1 + v2, s2 = v1*v1 + v2*v2;
        #pragma unroll
        for (int o = 16; o; o >>= 1){ s += __shfl_xor_sync(~0u, s, o); s2 += __shfl_xor_sync(~0u, s2, o); }
        float mu = s * (1.f/64.f);
        float rs = rsqrtf(s2 * (1.f/64.f) - mu*mu + 1e-5f);
        s_ecT[lane*16 + r]      = (v1 - mu) * rs * ec_g[lane]      + ec_b[lane];
        s_ecT[(lane+32)*16 + r] = (v2 - mu) * rs * ec_g[lane + 32] + ec_b[lane + 32];
    }
    __syncthreads();

    // ---- Stages 2-4: two passes of 8 rows: proj GEMM + LN + 3-pass radix top-81 ----
    const int rq = (tid >> 7) * 4;   // proj row sub-group (0 or 4)
    for (int p = 0; p < 2; ++p){
        for (int nt = 0; nt < 8; ++nt){
            int ca = nt * 256 + c0, cb = ca + 128;
            float bpa = b_pp[ca], bpb = b_pp[cb];
            float a0[4] = {bpa, bpa, bpa, bpa};
            float a1[4] = {bpb, bpb, bpb, bpb};
            #pragma unroll 4
            for (int k4 = 0; k4 < 16; ++k4){
                float4 wa = g_Wpp4[k4 * NDG + ca];
                float4 wb = g_Wpp4[k4 * NDG + cb];
                #pragma unroll
                for (int jj = 0; jj < 4; ++jj){
                    float4 v = *(const float4*)(s_ecT + (4*k4+jj)*16 + p*8 + rq);
                    float wA = jj==0?wa.x:jj==1?wa.y:jj==2?wa.z:wa.w;
                    float wB = jj==0?wb.x:jj==1?wb.y:jj==2?wb.z:wb.w;
                    a0[0]=fmaf(v.x,wA,a0[0]); a0[1]=fmaf(v.y,wA,a0[1]);
                    a0[2]=fmaf(v.z,wA,a0[2]); a0[3]=fmaf(v.w,wA,a0[3]);
                    a1[0]=fmaf(v.x,wB,a1[0]); a1[1]=fmaf(v.y,wB,a1[1]);
                    a1[2]=fmaf(v.z,wB,a1[2]); a1[3]=fmaf(v.w,wB,a1[3]);
                }
            }
            #pragma unroll
            for (int i = 0; i < 4; ++i){
                pool[(rq+i)*NDG + ca] = fmaxf(a0[i], 0.f);
                pool[(rq+i)*NDG + cb] = fmaxf(a1[i], 0.f);
            }
        }
        __syncthreads();

        // 1 row per warp: LN + 3-pass radix (24-bit threshold) + compaction
        {
            unsigned* hist = s_hist + w * 256;
            int rg  = p * 8 + w;
            float* row = pool + w * NDG;
            float s = 0.f, s2 = 0.f;
            for (int i = lane; i < NDG; i += 32){ float v = row[i]; s += v; s2 += v*v; }
            #pragma unroll
            for (int o = 16; o; o >>= 1){ s += __shfl_xor_sync(~0u, s, o); s2 += __shfl_xor_sync(~0u, s2, o); }
            float mu = s * (1.f/2048.f);
            float rs = rsqrtf(s2 * (1.f/2048.f) - mu*mu + 1e-5f);
            for (int i = lane; i < NDG; i += 32)
                row[i] = (row[i] - mu) * rs * dg_g[i] + dg_b[i];
            __syncwarp();

            unsigned prefix = 0; int need = KACT;
            for (int pp = 3; pp >= 1; --pp){
                for (int b = lane; b < 256; b += 32) hist[b] = 0;
                __syncwarp();
                unsigned himask = (pp == 3) ? 0u : (0xFFFFFFFFu << ((pp + 1) * 8));
                for (int i = lane; i < NDG; i += 32){
                    unsigned uu = f2u(row[i]);
                    if ((uu & himask) == prefix) atomicAdd(&hist[(uu >> (pp*8)) & 255], 1u);
                }
                __syncwarp();
                int b0 = 255 - lane * 8;
                unsigned cs[8]; unsigned cnt = 0;
                #pragma unroll
                for (int t = 0; t < 8; ++t){ cs[t] = hist[b0 - t]; cnt += cs[t]; }
                unsigned inc = cnt;
                #pragma unroll
                for (int o = 1; o < 32; o <<= 1){ unsigned v = __shfl_up_sync(~0u, inc, o); if (lane >= o) inc += v; }
                unsigned excl = inc - cnt;
                bool hit = (excl < (unsigned)need) && ((unsigned)need <= inc);
                unsigned bal = __ballot_sync(~0u, hit);
                int srcl = __ffs(bal) - 1;
                int selbin = 0, newneed = 0, found = 0;
                if (hit){
                    unsigned cum = excl;
                    #pragma unroll
                    for (int t = 0; t < 8; ++t){
                        unsigned nc = cum + cs[t];
                        if (!found && nc >= (unsigned)need){ selbin = b0 - t; newneed = need - (int)cum; found = 1; }
                        cum = nc;
                    }
                }
                selbin = __shfl_sync(~0u, selbin, srcl);
                need   = __shfl_sync(~0u, newneed, srcl);
                prefix |= ((unsigned)selbin) << (pp * 8);
            }

            int base = 0, ties = 0;
            for (int g = 0; g < 64; ++g){
                int c = g * 32 + lane;
                float v = row[c];
                unsigned uu = f2u(v) & 0xFFFFFF00u;
                bool eq = (uu == prefix);
                bool gt = (uu >  prefix);
                unsigned beq = __ballot_sync(~0u, eq);
                int tr = ties + __popc(beq & lmask);
                bool act = gt || (eq && tr < need);
                unsigned ba = __ballot_sync(~0u, act);
                if (act){
                    int pos = base + __popc(ba & lmask);
                    s_act[rg*84 + pos] = make_float2(v, __int_as_float(c << 8));
                }
                base += __popc(ba);
                ties += __popc(beq);
            }
        }
        __syncthreads();
    }

    // ---- Stage 5: cue = sparse(dg) @ WmossyT -> B1[256][STR] ----
    {
        float acc[16];
        #pragma unroll
        for (int r = 0; r < 16; ++r) acc[r] = 0.f;
        #pragma unroll 2
        for (int a = 0; a < KACT; ++a){
            #pragma unroll
            for (int r = 0; r < 16; ++r){
                float2 pv = s_act[r*84 + a];
                acc[r] = fmaf(pv.x, g_WmossyT[__float_as_int(pv.y) + tid], acc[r]);
            }
        }
        float4* dp = (float4*)(B1 + tid*STR);
        dp[0] = make_float4(acc[0], acc[1], acc[2], acc[3]);
        dp[1] = make_float4(acc[4], acc[5], acc[6], acc[7]);
        dp[2] = make_float4(acc[8], acc[9], acc[10], acc[11]);
        dp[3] = make_float4(acc[12], acc[13], acc[14], acc[15]);
    }
    __syncthreads();

    // ---- Stage 6: 5-step settle; z = state@(1.4*Wrec)^T + 0.6*cue; tanh via exp(z) ----
    float cuev[16];
    {
        const float4* ca = (const float4*)(B1 + c0*STR + rb);
        const float4* cb = (const float4*)(B1 + (c0+128)*STR + rb);
        float4 x0 = ca[0], x1 = ca[1], y0 = cb[0], y1 = cb[1];
        cuev[0]=0.6f*x0.x; cuev[1]=0.6f*x0.y; cuev[2]=0.6f*x0.z; cuev[3]=0.6f*x0.w;
        cuev[4]=0.6f*x1.x; cuev[5]=0.6f*x1.y; cuev[6]=0.6f*x1.z; cuev[7]=0.6f*x1.w;
        cuev[8]=0.6f*y0.x; cuev[9]=0.6f*y0.y; cuev[10]=0.6f*y0.z; cuev[11]=0.6f*y0.w;
        cuev[12]=0.6f*y1.x; cuev[13]=0.6f*y1.y; cuev[14]=0.6f*y1.z; cuev[15]=0.6f*y1.w;
    }
    const float* cur = B1;
    float* nxt = B2;
    for (int it = 0; it < 5; ++it){
        float acc[16];
        #pragma unroll
        for (int r = 0; r < 16; ++r) acc[r] = 0.f;
        gemv256(acc, cur, g_Wrec4, c0, rb);
        float res[16];
        #pragma unroll
        for (int r = 0; r < 16; ++r) res[r] = fast_tanh_z(acc[r] + cuev[r]);
        store2x8(nxt, res, c0, rb);
        __syncthreads();
        if (it == 0){ cur = B2; nxt = B3; }
        else { float* t = (float*)cur; cur = nxt; nxt = t; }
    }
    // final state in B2

    // ---- Stages 8+10 fused: 4 GEMVs in 2 paired passes (shared value reads) ----
    float accA[16], accB[16];
    {
        // pair 1 over B2: acc_s (Wcssc) + accB (Wogsc)
        float acc_s[16];
        {
            float sa = g_bcssc[c0],  sb = g_bcssc[c0 + 128];
            float oa = g_b2ogsc[c0], ob = g_b2ogsc[c0 + 128];
            #pragma unroll
            for (int r = 0; r < 8; ++r){
                acc_s[r] = sa; acc_s[r+8] = sb;
                accB[r]  = oa; accB[r+8]  = ob;
            }
        }
        gemv256_pair(acc_s, accB, B2, g_Wcssc4, g_Wogsc4, c0, rb);

        // pair 2 over s_ecT: acc_d (Wcdta) + accA (Wogta)
        float acc_d[16];
        {
            float da = g_btap[c0],   db = g_btap[c0 + 128];
            float oa = g_b2ogta[c0], ob = g_b2ogta[c0 + 128];
            #pragma unroll
            for (int r = 0; r < 8; ++r){
                acc_d[r] = da; acc_d[r+8] = db;
                accA[r]  = oa; accA[r+8]  = ob;
            }
        }
        gemv64_pair(acc_d, accA, s_ecT, g_Wcdta4, g_Wogta4, c0, rb);

        // novelty partials from acc_s / acc_d
        #pragma unroll
        for (int i = 0; i < 8; ++i){
            float sd = acc_s[i]*acc_d[i] + acc_s[i+8]*acc_d[i+8];
            float sn = acc_s[i]*acc_s[i] + acc_s[i+8]*acc_s[i+8];
            float dn = acc_d[i]*acc_d[i] + acc_d[i+8]*acc_d[i+8];
            #pragma unroll
            for (int o = 16; o; o >>= 1){
                sd += __shfl_xor_sync(~0u, sd, o);
                sn += __shfl_xor_sync(~0u, sn, o);
                dn += __shfl_xor_sync(~0u, dn, o);
            }
            if (lane == 0){
                s_red[w*24 + i*3 + 0] = sd;
                s_red[w*24 + i*3 + 1] = sn;
                s_red[w*24 + i*3 + 2] = dn;
            }
        }
    }
    __syncthreads();
    if (tid < 16){
        int r = tid, rl = r & 7, wb = (r >> 3) * 4;
        float sd = 0.f, sn = 0.f, dn = 0.f;
        #pragma unroll
        for (int q = 0; q < 4; ++q){
            sd += s_red[(wb+q)*24 + rl*3 + 0];
            sn += s_red[(wb+q)*24 + rl*3 + 1];
            dn += s_red[(wb+q)*24 + rl*3 + 2];
        }
        float s_n = fmaxf(sqrtf(sn), 1e-8f);
        float d_n = fmaxf(sqrtf(dn), 1e-8f);
        float cosv = sd / (s_n * d_n);
        float nov = fminf(fmaxf(1.f - cosv, 0.f), 1.f);
        s_nov[r] = nov;
        out[(long long)NB * NCA + row0 + r] = nov;
    }
    __syncthreads();

    // ---- epilogue: out = tanh( g*A + (1-g)*B ), 2x and b_og folded in A,B ----
    {
        float4 g0 = *(const float4*)(s_nov + rb);
        float4 g1 = *(const float4*)(s_nov + rb + 4);
        float gts[8] = {g0.x, g0.y, g0.z, g0.w, g1.x, g1.y, g1.z, g1.w};
        #pragma unroll
        for (int i = 0; i < 8; ++i){
            float g = gts[i];
            float za = fmaf(g, accA[i],   (1.f - g) * accB[i]);
            float zb = fmaf(g, accA[i+8], (1.f - g) * accB[i+8]);
            out[(long long)(row0 + rb + i) * NCA + c0]       = fast_tanh_z(za);
            out[(long long)(row0 + rb + i) * NCA + c0 + 128] = fast_tanh_z(zb);
        }
    }
}

// ---------------- launch ----------------
extern "C" void kernel_launch(void* const* d_in, const int* in_sizes, int n_in,
                              void* d_out, int out_size)
{
    const float* coords = (const float*)d_in[0];
    const float* ec_g   = (const float*)d_in[1];
    const float* ec_b   = (const float*)d_in[2];
    const float* W_pp   = (const float*)d_in[3];
    const float* b_pp   = (const float*)d_in[4];
    const float* dg_g   = (const float*)d_in[5];
    const float* dg_b   = (const float*)d_in[6];
    const float* W_mo   = (const float*)d_in[7];
    const float* W_rec  = (const float*)d_in[8];
    const float* W_sc   = (const float*)d_in[9];
    const float* b_sc   = (const float*)d_in[10];
    const float* W_ta   = (const float*)d_in[11];
    const float* b_ta   = (const float*)d_in[12];
    const float* W_cs   = (const float*)d_in[13];
    const float* W_cd   = (const float*)d_in[14];
    const float* W_og   = (const float*)d_in[15];
    const float* b_og   = (const float*)d_in[16];
    float* out = (float*)d_out;

    const size_t smem = (size_t)(16384 + 1024 + 2688 + 2048 + 256 + 64 + 16 + 192) * 4;  // 90,688 B
    static int configured = 0;
    if (!configured){
        cudaFuncSetAttribute(fused_kernel, cudaFuncAttributeMaxDynamicSharedMemorySize, (int)smem);
        configured = 1;
    }

    prep_kernel<<<896, 256>>>(coords, W_pp, W_mo, W_rec);
    prep_gemm<<<164, 256>>>(W_cs, W_cd, W_og, W_sc, W_ta, b_ta, b_sc, b_og);
    fused_kernel<<<NB / MR, NTHR, smem>>>(coords, ec_g, ec_b, b_pp, dg_g, dg_b, out);
}

// round 12
// speedup vs baseline: 1.2359x; 1.0932x over previous
#include <cuda_runtime.h>

#define NB   32768
#define NCO  64
#define NDG  2048
#define NCA  256
#define KACT 81
#define MR   16
#define NTHR 256
#define STR  16   // float stride of [256 col][16 row] tiles

typedef unsigned long long u64;

// ---------------- device-global scratch ----------------
__device__ float4 g_Wpp4[16 * NDG];      // [k4][c]
__device__ float  g_WmossyT[NDG * NCA];  // [d][c]
__device__ float4 g_Wrec4[64 * NCA];     // [j4][c], pre-scaled by 1.4 (=2*GAIN)
__device__ float4 g_Wcssc4[64 * NCA];    // (Wcs @ Wsc)
__device__ float4 g_Wogsc4[64 * NCA];    // 2*(Wog @ Wsc)
__device__ float4 g_Wogta4[16 * NCA];    // 2*(Wog @ Wta)
__device__ float4 g_Wcdta4[16 * NCA];    // (Wcd @ Wta)
__device__ float  g_btap[NCA];           // Wcd @ b_ta
__device__ float  g_bcssc[NCA];          // Wcs @ b_sc
__device__ float  g_b2ogta[NCA];         // 2*(Wog @ b_ta) + 2*b_og
__device__ float  g_b2ogsc[NCA];         // 2*(Wog @ b_sc) + 2*b_og
__device__ float  g_part[256 * NCO];

// ---------------- f32x2 packed helpers ----------------
__device__ __forceinline__ u64 pk2(float v){
    u64 r; asm("mov.b64 %0, {%1, %1};" : "=l"(r) : "f"(v)); return r;
}
__device__ __forceinline__ void upk(u64 p, float& a, float& b){
    asm("mov.b64 {%0, %1}, %2;" : "=f"(a), "=f"(b) : "l"(p));
}
__device__ __forceinline__ void fma2(u64& acc, u64 v, u64 w){
    asm("fma.rn.f32x2 %0, %1, %2, %0;" : "+l"(acc) : "l"(v), "l"(w));
}

// order-preserving float->uint key
__device__ __forceinline__ unsigned f2u(float f){
    unsigned u = __float_as_uint(f);
    return u ^ ((u & 0x80000000u) ? 0xFFFFFFFFu : 0x80000000u);
}

// tanh where z = 2x is already applied: tanh(x) = 1 - 2/(exp(2x)+1)
__device__ __forceinline__ float fast_tanh_z(float z){
    float e = __expf(z);
    return 1.f - __fdividef(2.f, e + 1.f);
}

// 2 cols x 8 rows packed: acc[0..3]=colA row-pairs, acc[4..7]=colB; 2 LDS.128 per 16 MACs
__device__ __forceinline__ void fma2x8_u(u64 acc[8], const float* __restrict__ sT,
                                         u64 wA, u64 wB){
    const ulonglong2* e = (const ulonglong2*)sT;
    ulonglong2 v0 = e[0], v1 = e[1];
    fma2(acc[0], v0.x, wA); fma2(acc[1], v0.y, wA);
    fma2(acc[2], v1.x, wA); fma2(acc[3], v1.y, wA);
    fma2(acc[4], v0.x, wB); fma2(acc[5], v0.y, wB);
    fma2(acc[6], v1.x, wB); fma2(acc[7], v1.y, wB);
}

// paired variant: two accumulator sets share one value load
__device__ __forceinline__ void fma2x8_pair_u(u64 P[8], u64 Q[8],
                                              const float* __restrict__ sT,
                                              u64 pA, u64 pB, u64 qA, u64 qB){
    const ulonglong2* e = (const ulonglong2*)sT;
    ulonglong2 v0 = e[0], v1 = e[1];
    fma2(P[0], v0.x, pA); fma2(P[1], v0.y, pA);
    fma2(P[2], v1.x, pA); fma2(P[3], v1.y, pA);
    fma2(P[4], v0.x, pB); fma2(P[5], v0.y, pB);
    fma2(P[6], v1.x, pB); fma2(P[7], v1.y, pB);
    fma2(Q[0], v0.x, qA); fma2(Q[1], v0.y, qA);
    fma2(Q[2], v1.x, qA); fma2(Q[3], v1.y, qA);
    fma2(Q[4], v0.x, qB); fma2(Q[5], v0.y, qB);
    fma2(Q[6], v1.x, qB); fma2(Q[7], v1.y, qB);
}

// GEMV over 256 inputs: thread covers cols (c0, c0+128), rows rb..rb+7, packed accs
__device__ __forceinline__ void gemv256_u(u64 acc[8], const float* __restrict__ src,
                                          const float4* __restrict__ w4, int c0, int rb){
    #pragma unroll 4
    for (int j4 = 0; j4 < 64; ++j4){
        float4 wa = w4[j4 * NCA + c0];
        float4 wb = w4[j4 * NCA + c0 + 128];
        fma2x8_u(acc, src + (4*j4+0)*STR + rb, pk2(wa.x), pk2(wb.x));
        fma2x8_u(acc, src + (4*j4+1)*STR + rb, pk2(wa.y), pk2(wb.y));
        fma2x8_u(acc, src + (4*j4+2)*STR + rb, pk2(wa.z), pk2(wb.z));
        fma2x8_u(acc, src + (4*j4+3)*STR + rb, pk2(wa.w), pk2(wb.w));
    }
}

// paired GEMV over 256 inputs
__device__ __forceinline__ void gemv256_pair_u(u64 P[8], u64 Q[8],
                                               const float* __restrict__ src,
                                               const float4* __restrict__ wp,
                                               const float4* __restrict__ wq,
                                               int c0, int rb){
    #pragma unroll 2
    for (int j4 = 0; j4 < 64; ++j4){
        float4 pa = wp[j4 * NCA + c0];
        float4 pb = wp[j4 * NCA + c0 + 128];
        float4 qa = wq[j4 * NCA + c0];
        float4 qb = wq[j4 * NCA + c0 + 128];
        fma2x8_pair_u(P, Q, src + (4*j4+0)*STR + rb, pk2(pa.x), pk2(pb.x), pk2(qa.x), pk2(qb.x));
        fma2x8_pair_u(P, Q, src + (4*j4+1)*STR + rb, pk2(pa.y), pk2(pb.y), pk2(qa.y), pk2(qb.y));
        fma2x8_pair_u(P, Q, src + (4*j4+2)*STR + rb, pk2(pa.z), pk2(pb.z), pk2(qa.z), pk2(qb.z));
        fma2x8_pair_u(P, Q, src + (4*j4+3)*STR + rb, pk2(pa.w), pk2(pb.w), pk2(qa.w), pk2(qb.w));
    }
}

// paired GEMV over 64 inputs (reads s_ecT [64][16])
__device__ __forceinline__ void gemv64_pair_u(u64 P[8], u64 Q[8],
                                              const float* __restrict__ src,
                                              const float4* __restrict__ wp,
                                              const float4* __restrict__ wq,
                                              int c0, int rb){
    #pragma unroll 2
    for (int k4 = 0; k4 < 16; ++k4){
        float4 pa = wp[k4 * NCA + c0];
        float4 pb = wp[k4 * NCA + c0 + 128];
        float4 qa = wq[k4 * NCA + c0];
        float4 qb = wq[k4 * NCA + c0 + 128];
        fma2x8_pair_u(P, Q, src + (4*k4+0)*16 + rb, pk2(pa.x), pk2(pb.x), pk2(qa.x), pk2(qb.x));
        fma2x8_pair_u(P, Q, src + (4*k4+1)*16 + rb, pk2(pa.y), pk2(pb.y), pk2(qa.y), pk2(qb.y));
        fma2x8_pair_u(P, Q, src + (4*k4+2)*16 + rb, pk2(pa.z), pk2(pb.z), pk2(qa.z), pk2(qb.z));
        fma2x8_pair_u(P, Q, src + (4*k4+3)*16 + rb, pk2(pa.w), pk2(pb.w), pk2(qa.w), pk2(qb.w));
    }
}

__device__ __forceinline__ void store2x8(float* __restrict__ dst, const float acc[16],
                                         int c0, int rb){
    float4* d0 = (float4*)(dst + c0*STR + rb);
    float4* d1 = (float4*)(dst + (c0+128)*STR + rb);
    d0[0] = make_float4(acc[0], acc[1], acc[2], acc[3]);
    d0[1] = make_float4(acc[4], acc[5], acc[6], acc[7]);
    d1[0] = make_float4(acc[8], acc[9], acc[10], acc[11]);
    d1[1] = make_float4(acc[12], acc[13], acc[14], acc[15]);
}

// unpack 8 packed accs (2col x 8row) into 16 floats: [0..7]=colA rows, [8..15]=colB rows
__device__ __forceinline__ void upk8(const u64 acc[8], float out[16]){
    upk(acc[0], out[0],  out[1]);  upk(acc[1], out[2],  out[3]);
    upk(acc[2], out[4],  out[5]);  upk(acc[3], out[6],  out[7]);
    upk(acc[4], out[8],  out[9]);  upk(acc[5], out[10], out[11]);
    upk(acc[6], out[12], out[13]); upk(acc[7], out[14], out[15]);
}

// ---------------- prep kernel: coalesced relayouts + column partial sums ----------------
__global__ void prep_kernel(const float* __restrict__ coords,
                            const float* __restrict__ W_pp, const float* __restrict__ W_mo,
                            const float* __restrict__ W_rec)
{
    __shared__ float sh[32 * 65];
    const int b = blockIdx.x, tid = threadIdx.x;
    const int tx = tid & 31, ty = tid >> 5;   // 32 x 8

    if (b < 256){
        __shared__ float s[4][64];
        int c = tid & 63, g = tid >> 6;
        int r0 = b * 128 + g * 32;
        float acc = 0.f;
        #pragma unroll 8
        for (int i = 0; i < 32; ++i) acc += coords[(r0 + i) * 64 + c];
        s[g][c] = acc;
        __syncthreads();
        if (g == 0) g_part[b * 64 + c] = s[0][c] + s[1][c] + s[2][c] + s[3][c];
    } else if (b < 768){
        int b2 = b - 256;
        int ci = b2 & 7, di = b2 >> 3;
        #pragma unroll
        for (int i = 0; i < 4; ++i){
            int cc = ty + 8 * i;
            sh[cc * 33 + tx] = W_mo[(ci * 32 + cc) * 2048 + di * 32 + tx];
        }
        __syncthreads();
        #pragma unroll
        for (int i = 0; i < 4; ++i){
            int dd = ty + 8 * i;
            g_WmossyT[(di * 32 + dd) * 256 + ci * 32 + tx] = sh[tx * 33 + dd];
        }
    } else if (b < 832){
        int c0 = (b - 768) * 32;
        #pragma unroll
        for (int i = 0; i < 8; ++i){
            int idx = i * 256 + tid;
            int row = idx >> 6, col = idx & 63;
            sh[row * 65 + col] = W_pp[(c0 + row) * 64 + col];
        }
        __syncthreads();
        #pragma unroll
        for (int oi = 0; oi < 2; ++oi){
            int idx = oi * 256 + tid;
            int k4 = idx >> 5, c = idx & 31;
            float4 v = make_float4(sh[c * 65 + 4*k4], sh[c * 65 + 4*k4 + 1],
                                   sh[c * 65 + 4*k4 + 2], sh[c * 65 + 4*k4 + 3]);
            g_Wpp4[k4 * NDG + c0 + c] = v;
        }
    } else {
        int b4 = b - 832;
        int ci = b4 & 7, ji = b4 >> 3;
        #pragma unroll
        for (int i = 0; i < 4; ++i){
            int cc = ty + 8 * i;
            sh[cc * 33 + tx] = W_rec[(ci * 32 + cc) * 256 + ji * 32 + tx];
        }
        __syncthreads();
        {
            int j4l = ty, c = tx;
            float4 v = make_float4(1.4f * sh[c * 33 + 4*j4l],     1.4f * sh[c * 33 + 4*j4l + 1],
                                   1.4f * sh[c * 33 + 4*j4l + 2], 1.4f * sh[c * 33 + 4*j4l + 3]);
            g_Wrec4[(ji * 8 + j4l) * NCA + ci * 32 + c] = v;
        }
    }
}

// ---------------- tiled GEMM prep + bias dots ----------------
__global__ void prep_gemm(const float* __restrict__ W_cs, const float* __restrict__ W_cd,
                          const float* __restrict__ W_og,
                          const float* __restrict__ W_sc, const float* __restrict__ W_ta,
                          const float* __restrict__ b_ta, const float* __restrict__ b_sc,
                          const float* __restrict__ b_og)
{
    int b = blockIdx.x;
    int tx = threadIdx.x & 31;
    int ty = threadIdx.x >> 5;

    if (b >= 160){
        int t = b - 160;
        const float* A   = (t==0) ? W_cd : (t==1) ? W_cs : W_og;
        const float* vec = (t==0) ? b_ta : (t==1) ? b_sc : (t==2) ? b_ta : b_sc;
        float* dst = (t==0) ? g_btap : (t==1) ? g_bcssc : (t==2) ? g_b2ogta : g_b2ogsc;
        float scale = (t < 2) ? 1.f : 2.f;
        for (int c = ty; c < 256; c += 8){
            float acc = 0.f;
            #pragma unroll
            for (int kt = 0; kt < 8; ++kt)
                acc = fmaf(A[c * 256 + kt * 32 + tx], vec[kt * 32 + tx], acc);
            #pragma unroll
            for (int o = 16; o; o >>= 1) acc += __shfl_xor_sync(~0u, acc, o);
            if (tx == 0) dst[c] = scale * acc + ((t >= 2) ? 2.f * b_og[c] : 0.f);
        }
        return;
    }

    __shared__ float As[32][33];
    __shared__ float Bs[32][33];

    const float *A, *B; float* dst; float scale; int ldb, jtiles;
    if (b < 64)      { A = W_cs; B = W_sc; dst = (float*)g_Wcssc4; scale = 1.f; ldb = 256; jtiles = 8; }
    else if (b < 128){ A = W_og; B = W_sc; dst = (float*)g_Wogsc4; scale = 2.f; ldb = 256; jtiles = 8; b -= 64; }
    else if (b < 144){ A = W_og; B = W_ta; dst = (float*)g_Wogta4; scale = 2.f; ldb = 64;  jtiles = 2; b -= 128; }
    else             { A = W_cd; B = W_ta; dst = (float*)g_Wcdta4; scale = 1.f; ldb = 64;  jtiles = 2; b -= 144; }

    int ci = b / jtiles, ji = b % jtiles;
    float acc[4] = {0.f, 0.f, 0.f, 0.f};
    for (int kt = 0; kt < 8; ++kt){
        #pragma unroll
        for (int ii = 0; ii < 4; ++ii){
            int rr = ty + 8 * ii;
            As[rr][tx] = A[(ci * 32 + rr) * 256 + kt * 32 + tx];
            Bs[rr][tx] = B[(kt * 32 + rr) * ldb + ji * 32 + tx];
        }
        __syncthreads();
        #pragma unroll
        for (int kk = 0; kk < 32; ++kk){
            float bv = Bs[kk][tx];
            #pragma unroll
            for (int ii = 0; ii < 4; ++ii)
                acc[ii] = fmaf(As[ty + 8 * ii][kk], bv, acc[ii]);
        }
        __syncthreads();
    }

    #pragma unroll
    for (int ii = 0; ii < 4; ++ii)
        As[ty + 8 * ii][tx] = scale * acc[ii];
    __syncthreads();
    {
        int j4l = ty, cl = tx;
        int j0 = ji * 32 + j4l * 4;
        float4 v = make_float4(As[cl][j4l*4], As[cl][j4l*4+1], As[cl][j4l*4+2], As[cl][j4l*4+3]);
        ((float4*)dst)[(j0 >> 2) * NCA + ci * 32 + cl] = v;
    }
}

// ---------------- fused pipeline: 16 rows per block, 2 blocks/SM ----------------
extern "C" __global__ void __launch_bounds__(NTHR, 2)
fused_kernel(const float* __restrict__ coords,
             const float* __restrict__ ec_g,  const float* __restrict__ ec_b,
             const float* __restrict__ b_pp,
             const float* __restrict__ dg_g,  const float* __restrict__ dg_b,
             float* __restrict__ out)
{
    extern __shared__ float sm[];
    float*    B1       = sm;
    float*    B2       = sm + 4096;
    float*    B3       = sm + 8192;
    float*    pool     = sm;                      // union with B1..B3 + 4096 extra
    float*    s_ecT    = sm + 16384;              // [64][16] = 1024
    float2*   s_act    = (float2*)(sm + 17408);   // 16 x 84 float2 = 2688 floats
    unsigned* s_hist   = (unsigned*)(sm + 20096); // 8 x 256 = 2048
    float*    s_tmp    = sm + 22144;              // 256
    float*    s_bufadd = sm + 22400;              // 64
    float*    s_nov    = sm + 22464;              // 16
    float*    s_red    = sm + 22480;              // 8 warps x 24 = 192

    const int tid  = threadIdx.x;
    const int w    = tid >> 5;
    const int lane = tid & 31;
    const unsigned lmask = (1u << lane) - 1u;
    const int row0 = blockIdx.x * MR;
    const int c0   = tid & 127;          // col pair (c0, c0+128)
    const int rb   = (tid >> 7) * 8;     // row group (0 or 8)

    // ---- Stage 0: reduce column partials -> s_bufadd ----
    {
        int c = tid & 63, q = tid >> 6;
        float a = 0.f;
        #pragma unroll 8
        for (int i = 0; i < 64; ++i) a += g_part[(q * 64 + i) * 64 + c];
        s_tmp[q * 64 + c] = a;
        __syncthreads();
        if (tid < 64)
            s_bufadd[tid] = (0.05f / (float)NB) *
                (s_tmp[tid] + s_tmp[64 + tid] + s_tmp[128 + tid] + s_tmp[192 + tid]);
        __syncthreads();
    }

    // ---- Stage 1: EC layernorm (2 rows/warp) -> s_ecT[64][16] ----
    for (int rr = 0; rr < 2; ++rr){
        int r  = w * 2 + rr;
        int gr = row0 + r;
        float v1 = coords[gr*64 + lane]      + s_bufadd[lane];
        float v2 = coords[gr*64 + lane + 32] + s_bufadd[lane + 32];
        float s = v1 + v2, s2 = v1*v1 + v2*v2;
        #pragma unroll
        for (int o = 16; o; o >>= 1){ s += __shfl_xor_sync(~0u, s, o); s2 += __shfl_xor_sync(~0u, s2, o); }
        float mu = s * (1.f/64.f);
        float rs = rsqrtf(s2 * (1.f/64.f) - mu*mu + 1e-5f);
        s_ecT[lane*16 + r]      = (v1 - mu) * rs * ec_g[lane]      + ec_b[lane];
        s_ecT[(lane+32)*16 + r] = (v2 - mu) * rs * ec_g[lane + 32] + ec_b[lane + 32];
    }
    __syncthreads();

    // ---- Stages 2-4: two passes of 8 rows: proj GEMM + LN + 3-pass radix top-81 ----
    const int rq = (tid >> 7) * 4;   // proj row sub-group (0 or 4)
    for (int p = 0; p < 2; ++p){
        for (int nt = 0; nt < 8; ++nt){
            int ca = nt * 256 + c0, cb = ca + 128;
            u64 a0[2], a1[2];
            a0[0] = a0[1] = pk2(b_pp[ca]);
            a1[0] = a1[1] = pk2(b_pp[cb]);
            #pragma unroll 4
            for (int k4 = 0; k4 < 16; ++k4){
                float4 wa = g_Wpp4[k4 * NDG + ca];
                float4 wb = g_Wpp4[k4 * NDG + cb];
                #pragma unroll
                for (int jj = 0; jj < 4; ++jj){
                    ulonglong2 v = *(const ulonglong2*)(s_ecT + (4*k4+jj)*16 + p*8 + rq);
                    float wA = jj==0?wa.x:jj==1?wa.y:jj==2?wa.z:wa.w;
                    float wB = jj==0?wb.x:jj==1?wb.y:jj==2?wb.z:wb.w;
                    u64 wA2 = pk2(wA), wB2 = pk2(wB);
                    fma2(a0[0], v.x, wA2); fma2(a0[1], v.y, wA2);
                    fma2(a1[0], v.x, wB2); fma2(a1[1], v.y, wB2);
                }
            }
            float f0[4], f1[4];
            upk(a0[0], f0[0], f0[1]); upk(a0[1], f0[2], f0[3]);
            upk(a1[0], f1[0], f1[1]); upk(a1[1], f1[2], f1[3]);
            #pragma unroll
            for (int i = 0; i < 4; ++i){
                pool[(rq+i)*NDG + ca] = fmaxf(f0[i], 0.f);
                pool[(rq+i)*NDG + cb] = fmaxf(f1[i], 0.f);
            }
        }
        __syncthreads();

        // 1 row per warp: LN + 3-pass radix (24-bit threshold) + compaction
        {
            unsigned* hist = s_hist + w * 256;
            int rg  = p * 8 + w;
            float* row = pool + w * NDG;
            float s = 0.f, s2 = 0.f;
            for (int i = lane; i < NDG; i += 32){ float v = row[i]; s += v; s2 += v*v; }
            #pragma unroll
            for (int o = 16; o; o >>= 1){ s += __shfl_xor_sync(~0u, s, o); s2 += __shfl_xor_sync(~0u, s2, o); }
            float mu = s * (1.f/2048.f);
            float rs = rsqrtf(s2 * (1.f/2048.f) - mu*mu + 1e-5f);
            for (int i = lane; i < NDG; i += 32)
                row[i] = (row[i] - mu) * rs * dg_g[i] + dg_b[i];
            __syncwarp();

            unsigned prefix = 0; int need = KACT;
            for (int pp = 3; pp >= 1; --pp){
                for (int b = lane; b < 256; b += 32) hist[b] = 0;
                __syncwarp();
                unsigned himask = (pp == 3) ? 0u : (0xFFFFFFFFu << ((pp + 1) * 8));
                for (int i = lane; i < NDG; i += 32){
                    unsigned uu = f2u(row[i]);
                    if ((uu & himask) == prefix) atomicAdd(&hist[(uu >> (pp*8)) & 255], 1u);
                }
                __syncwarp();
                int b0 = 255 - lane * 8;
                unsigned cs[8]; unsigned cnt = 0;
                #pragma unroll
                for (int t = 0; t < 8; ++t){ cs[t] = hist[b0 - t]; cnt += cs[t]; }
                unsigned inc = cnt;
                #pragma unroll
                for (int o = 1; o < 32; o <<= 1){ unsigned v = __shfl_up_sync(~0u, inc, o); if (lane >= o) inc += v; }
                unsigned excl = inc - cnt;
                bool hit = (excl < (unsigned)need) && ((unsigned)need <= inc);
                unsigned bal = __ballot_sync(~0u, hit);
                int srcl = __ffs(bal) - 1;
                int selbin = 0, newneed = 0, found = 0;
                if (hit){
                    unsigned cum = excl;
                    #pragma unroll
                    for (int t = 0; t < 8; ++t){
                        unsigned nc = cum + cs[t];
                        if (!found && nc >= (unsigned)need){ selbin = b0 - t; newneed = need - (int)cum; found = 1; }
                        cum = nc;
                    }
                }
                selbin = __shfl_sync(~0u, selbin, srcl);
                need   = __shfl_sync(~0u, newneed, srcl);
                prefix |= ((unsigned)selbin) << (pp * 8);
            }

            int base = 0, ties = 0;
            for (int g = 0; g < 64; ++g){
                int c = g * 32 + lane;
                float v = row[c];
                unsigned uu = f2u(v) & 0xFFFFFF00u;
                bool eq = (uu == prefix);
                bool gt = (uu >  prefix);
                unsigned beq = __ballot_sync(~0u, eq);
                int tr = ties + __popc(beq & lmask);
                bool act = gt || (eq && tr < need);
                unsigned ba = __ballot_sync(~0u, act);
                if (act){
                    int pos = base + __popc(ba & lmask);
                    s_act[rg*84 + pos] = make_float2(v, __int_as_float(c << 8));
                }
                base += __popc(ba);
                ties += __popc(beq);
            }
        }
        __syncthreads();
    }

    // ---- Stage 5: cue = sparse(dg) @ WmossyT -> B1[256][STR] ----
    {
        float acc[16];
        #pragma unroll
        for (int r = 0; r < 16; ++r) acc[r] = 0.f;
        #pragma unroll 2
        for (int a = 0; a < KACT; ++a){
            #pragma unroll
            for (int r = 0; r < 16; ++r){
                float2 pv = s_act[r*84 + a];
                acc[r] = fmaf(pv.x, g_WmossyT[__float_as_int(pv.y) + tid], acc[r]);
            }
        }
        float4* dp = (float4*)(B1 + tid*STR);
        dp[0] = make_float4(acc[0], acc[1], acc[2], acc[3]);
        dp[1] = make_float4(acc[4], acc[5], acc[6], acc[7]);
        dp[2] = make_float4(acc[8], acc[9], acc[10], acc[11]);
        dp[3] = make_float4(acc[12], acc[13], acc[14], acc[15]);
    }
    __syncthreads();

    // ---- Stage 6: 5-step settle; z = state@(1.4*Wrec)^T + 0.6*cue; tanh via exp(z) ----
    float cuev[16];
    {
        const float4* ca = (const float4*)(B1 + c0*STR + rb);
        const float4* cb = (const float4*)(B1 + (c0+128)*STR + rb);
        float4 x0 = ca[0], x1 = ca[1], y0 = cb[0], y1 = cb[1];
        cuev[0]=0.6f*x0.x; cuev[1]=0.6f*x0.y; cuev[2]=0.6f*x0.z; cuev[3]=0.6f*x0.w;
        cuev[4]=0.6f*x1.x; cuev[5]=0.6f*x1.y; cuev[6]=0.6f*x1.z; cuev[7]=0.6f*x1.w;
        cuev[8]=0.6f*y0.x; cuev[9]=0.6f*y0.y; cuev[10]=0.6f*y0.z; cuev[11]=0.6f*y0.w;
        cuev[12]=0.6f*y1.x; cuev[13]=0.6f*y1.y; cuev[14]=0.6f*y1.z; cuev[15]=0.6f*y1.w;
    }
    const float* cur = B1;
    float* nxt = B2;
    for (int it = 0; it < 5; ++it){
        u64 acc[8];
        #pragma unroll
        for (int q = 0; q < 8; ++q) acc[q] = 0ull;
        gemv256_u(acc, cur, g_Wrec4, c0, rb);
        float z[16];
        upk8(acc, z);
        float res[16];
        #pragma unroll
        for (int r = 0; r < 16; ++r) res[r] = fast_tanh_z(z[r] + cuev[r]);
        store2x8(nxt, res, c0, rb);
        __syncthreads();
        if (it == 0){ cur = B2; nxt = B3; }
        else { float* t = (float*)cur; cur = nxt; nxt = t; }
    }
    // final state in B2

    // ---- Stages 8+10 fused: 4 GEMVs in 2 paired passes (shared value reads) ----
    float fA[16], fB[16];
    {
        u64 acc_s[8], accB[8];
        {
            u64 sa = pk2(g_bcssc[c0]),  sb = pk2(g_bcssc[c0 + 128]);
            u64 oa = pk2(g_b2ogsc[c0]), ob = pk2(g_b2ogsc[c0 + 128]);
            #pragma unroll
            for (int q = 0; q < 4; ++q){
                acc_s[q] = sa; acc_s[q+4] = sb;
                accB[q]  = oa; accB[q+4]  = ob;
            }
        }
        gemv256_pair_u(acc_s, accB, B2, g_Wcssc4, g_Wogsc4, c0, rb);

        u64 acc_d[8], accA[8];
        {
            u64 da = pk2(g_btap[c0]),   db = pk2(g_btap[c0 + 128]);
            u64 oa = pk2(g_b2ogta[c0]), ob = pk2(g_b2ogta[c0 + 128]);
            #pragma unroll
            for (int q = 0; q < 4; ++q){
                acc_d[q] = da; acc_d[q+4] = db;
                accA[q]  = oa; accA[q+4]  = ob;
            }
        }
        gemv64_pair_u(acc_d, accA, s_ecT, g_Wcdta4, g_Wogta4, c0, rb);

        float fs[16], fd[16];
        upk8(acc_s, fs); upk8(acc_d, fd);
        upk8(accA, fA);  upk8(accB, fB);

        // novelty partials (fs/fd layout: [0..7]=colA rows, [8..15]=colB rows)
        #pragma unroll
        for (int i = 0; i < 8; ++i){
            float sd = fs[i]*fd[i] + fs[i+8]*fd[i+8];
            float sn = fs[i]*fs[i] + fs[i+8]*fs[i+8];
            float dn = fd[i]*fd[i] + fd[i+8]*fd[i+8];
            #pragma unroll
            for (int o = 16; o; o >>= 1){
                sd += __shfl_xor_sync(~0u, sd, o);
                sn += __shfl_xor_sync(~0u, sn, o);
                dn += __shfl_xor_sync(~0u, dn, o);
            }
            if (lane == 0){
                s_red[w*24 + i*3 + 0] = sd;
                s_red[w*24 + i*3 + 1] = sn;
                s_red[w*24 + i*3 + 2] = dn;
            }
        }
    }
    __syncthreads();
    if (tid < 16){
        int r = tid, rl = r & 7, wb = (r >> 3) * 4;
        float sd = 0.f, sn = 0.f, dn = 0.f;
        #pragma unroll
        for (int q = 0; q < 4; ++q){
            sd += s_red[(wb+q)*24 + rl*3 + 0];
            sn += s_red[(wb+q)*24 + rl*3 + 1];
            dn += s_red[(wb+q)*24 + rl*3 + 2];
        }
        float s_n = fmaxf(sqrtf(sn), 1e-8f);
        float d_n = fmaxf(sqrtf(dn), 1e-8f);
        float cosv = sd / (s_n * d_n);
        float nov = fminf(fmaxf(1.f - cosv, 0.f), 1.f);
        s_nov[r] = nov;
        out[(long long)NB * NCA + row0 + r] = nov;
    }
    __syncthreads();

    // ---- epilogue: out = tanh( g*A + (1-g)*B ), 2x and b_og folded in A,B ----
    {
        float4 g0 = *(const float4*)(s_nov + rb);
        float4 g1 = *(const float4*)(s_nov + rb + 4);
        float gts[8] = {g0.x, g0.y, g0.z, g0.w, g1.x, g1.y, g1.z, g1.w};
        #pragma unroll
        for (int i = 0; i < 8; ++i){
            float g = gts[i];
            float za = fmaf(g, fA[i],   (1.f - g) * fB[i]);
            float zb = fmaf(g, fA[i+8], (1.f - g) * fB[i+8]);
            out[(long long)(row0 + rb + i) * NCA + c0]       = fast_tanh_z(za);
            out[(long long)(row0 + rb + i) * NCA + c0 + 128] = fast_tanh_z(zb);
        }
    }
}

// ---------------- launch ----------------
extern "C" void kernel_launch(void* const* d_in, const int* in_sizes, int n_in,
                              void* d_out, int out_size)
{
    const float* coords = (const float*)d_in[0];
    const float* ec_g   = (const float*)d_in[1];
    const float* ec_b   = (const float*)d_in[2];
    const float* W_pp   = (const float*)d_in[3];
    const float* b_pp   = (const float*)d_in[4];
    const float* dg_g   = (const float*)d_in[5];
    const float* dg_b   = (const float*)d_in[6];
    const float* W_mo   = (const float*)d_in[7];
    const float* W_rec  = (const float*)d_in[8];
    const float* W_sc   = (const float*)d_in[9];
    const float* b_sc   = (const float*)d_in[10];
    const float* W_ta   = (const float*)d_in[11];
    const float* b_ta   = (const float*)d_in[12];
    const float* W_cs   = (const float*)d_in[13];
    const float* W_cd   = (const float*)d_in[14];
    const float* W_og   = (const float*)d_in[15];
    const float* b_og   = (const float*)d_in[16];
    float* out = (float*)d_out;

    const size_t smem = (size_t)(16384 + 1024 + 2688 + 2048 + 256 + 64 + 16 + 192) * 4;  // 90,688 B
    static int configured = 0;
    if (!configured){
        cudaFuncSetAttribute(fused_kernel, cudaFuncAttributeMaxDynamicSharedMemorySize, (int)smem);
        configured = 1;
    }

    prep_kernel<<<896, 256>>>(coords, W_pp, W_mo, W_rec);
    prep_gemm<<<164, 256>>>(W_cs, W_cd, W_og, W_sc, W_ta, b_ta, b_sc, b_og);
    fused_kernel<<<NB / MR, NTHR, smem>>>(coords, ec_g, ec_b, b_pp, dg_g, dg_b, out);
}